// round 1
// baseline (speedup 1.0000x reference)
#include <cuda_runtime.h>
#include <cuda_bf16.h>

// BaseSpanProposer: analytic span compaction.
// viable[b,s,l] = (s + l) < len_b  (l zero-based; len = l+1, end = s+l).
// jnp.nonzero order = ascending flattened (b,s,l) => closed-form mapping via
// per-batch prefix sums. Padding entries (i >= total) map to flat index 0.
//
// Output layout (assumed: reference tuple flattened+concatenated as float32):
//   [0,    N)    viable (0/1)
//   [N,   2N)    viable_batch_indices
//   [2N,  3N)    viable_starts
//   [3N,  4N)    viable_ends
//   [4N,  5N)    viable_lengths
//   [5N,  5N+NL) viable_unit_id_seqs (row-major [N, L])
//   [5N+NL, +N)  viable_p_weights
//   then start_candidates, end_candidates, len_candidates (N each)

#define MAXB 1024

__device__ int g_prefix[MAXB + 1];
__device__ int g_maxlen;

__global__ void span_scan_kernel(const int* __restrict__ lens, int B, int L) {
    __shared__ int cnt[MAXB];
    __shared__ int mx[256];
    int t = threadIdx.x;
    int localmax = 0;
    for (int b = t; b < B; b += blockDim.x) {
        int len = lens[b];
        if (len > localmax) localmax = len;
        int c;
        if (len >= L) c = (len - L + 1) * L + (L * (L - 1)) / 2;
        else          c = (len * (len + 1)) / 2;
        cnt[b] = c;
    }
    mx[t] = localmax;
    __syncthreads();
    if (t == 0) {
        int acc = 0;
        g_prefix[0] = 0;
        for (int b = 0; b < B; b++) { acc += cnt[b]; g_prefix[b + 1] = acc; }
        int m = 0;
        for (int k = 0; k < blockDim.x; k++) if (mx[k] > m) m = mx[k];
        g_maxlen = m;
    }
}

__global__ void span_fill_kernel(const int* __restrict__ seqs,
                                 const int* __restrict__ lens,
                                 const float* __restrict__ pw,
                                 float* __restrict__ out,
                                 int B, int S, int L, int N) {
    __shared__ int sp[MAXB + 1];
    __shared__ int sl[MAXB];
    for (int k = threadIdx.x; k <= B; k += blockDim.x) sp[k] = g_prefix[k];
    for (int k = threadIdx.x; k < B; k += blockDim.x) sl[k] = lens[k];
    __syncthreads();

    int i = blockIdx.x * blockDim.x + threadIdx.x;
    if (i >= N) return;

    const int total = sp[B];
    const int maxpos = g_maxlen - 1;

    // ---- row mapping: output row i -> (b, s, l) ----
    int b = 0, s = 0, l = 0;
    if (i < total) {
        int lo = 0, hi = B - 1;
        while (lo < hi) {
            int mid = (lo + hi + 1) >> 1;
            if (sp[mid] <= i) lo = mid; else hi = mid - 1;
        }
        b = lo;
        int j = i - sp[b];
        int len = sl[b];
        int full = len - L + 1;            // rows contributing L entries each
        if (full > 0 && j < full * L) {
            s = j / L;
            l = j - s * L;
        } else {
            int s0 = full > 0 ? full : 0;
            int jp = j - (full > 0 ? full * L : 0);
            int ss = s0, c = 0;
            while (true) {
                int cnt = len - ss; if (cnt > L) cnt = L;
                if (jp < c + cnt) { l = jp - c; break; }
                c += cnt; ss++;
            }
            s = ss;
        }
    }
    // padding rows keep (b,s,l) = (0,0,0): starts=0, ends=0, lengths=1, p=pw[0]

    // ---- candidate arrays: elementwise on flattened index i ----
    int SL = S * L;
    int bc = i / SL;
    int rem = i - bc * SL;
    int sc = rem / L;
    int lc = rem - sc * L;
    float viable_f = ((sc + lc) < sl[bc]) ? 1.0f : 0.0f;

    size_t Nz = (size_t)N;
    out[i]          = viable_f;
    out[Nz + i]     = (float)b;
    out[2 * Nz + i] = (float)s;
    out[3 * Nz + i] = (float)(s + l);
    out[4 * Nz + i] = (float)(l + 1);

    // ---- unit-id gather: 20 ints, clamped, vectorized float4 stores ----
    const int* row = seqs + (size_t)b * S;
    float* u = out + 5 * Nz + (size_t)i * L;
    if ((L & 3) == 0) {
        #pragma unroll 5
        for (int j = 0; j < L; j += 4) {
            float4 v;
            int p0 = s + j;     if (p0 > maxpos) p0 = maxpos;
            int p1 = s + j + 1; if (p1 > maxpos) p1 = maxpos;
            int p2 = s + j + 2; if (p2 > maxpos) p2 = maxpos;
            int p3 = s + j + 3; if (p3 > maxpos) p3 = maxpos;
            v.x = (float)row[p0];
            v.y = (float)row[p1];
            v.z = (float)row[p2];
            v.w = (float)row[p3];
            *(float4*)(u + j) = v;
        }
    } else {
        for (int j = 0; j < L; j++) {
            int p = s + j; if (p > maxpos) p = maxpos;
            u[j] = (float)row[p];
        }
    }

    size_t off6 = 5 * Nz + Nz * (size_t)L;
    out[off6 + i]          = pw[((size_t)b * S + s) * L + l];
    out[off6 + Nz + i]     = (float)sc;
    out[off6 + 2 * Nz + i] = (float)(sc + lc);
    out[off6 + 3 * Nz + i] = (float)(lc + 1);
}

extern "C" void kernel_launch(void* const* d_in, const int* in_sizes, int n_in,
                              void* d_out, int out_size) {
    const int* seqs = (const int*)d_in[0];   // (B, S) int32
    const int* lens = (const int*)d_in[1];   // (B,)   int32
    const float* pw = (const float*)d_in[2]; // (B, S, L) float32

    int B = in_sizes[1];
    int S = in_sizes[0] / B;
    int N = in_sizes[2];          // B*S*L
    int L = N / (B * S);
    float* out = (float*)d_out;

    span_scan_kernel<<<1, 256>>>(lens, B, L);
    int threads = 256;
    int blocks = (N + threads - 1) / threads;
    span_fill_kernel<<<blocks, threads>>>(seqs, lens, pw, out, B, S, L, N);
}

// round 2
// speedup vs baseline: 1.3876x; 1.3876x over previous
#include <cuda_runtime.h>
#include <cuda_bf16.h>

// BaseSpanProposer: analytic span compaction (see R1 notes).
// viable[b,s,l] = (s + l) < len_b. nonzero order = ascending flattened index,
// computable in closed form via per-batch prefix sums. Padding rows -> flat 0.
//
// R2: unit-id matrix stores transposed to block-cooperative contiguous writes
// (was: per-thread 80B-strided rows -> 20 lines per STG; now: 4 lines per STG).

#define MAXB 1024
#define TPB 256

__device__ int g_prefix[MAXB + 1];
__device__ int g_maxlen;

__global__ void span_scan_kernel(const int* __restrict__ lens, int B, int L) {
    __shared__ int cnt[MAXB];
    __shared__ int mx[TPB];
    int t = threadIdx.x;
    int localmax = 0;
    for (int b = t; b < B; b += blockDim.x) {
        int len = lens[b];
        if (len > localmax) localmax = len;
        int c;
        if (len >= L) c = (len - L + 1) * L + (L * (L - 1)) / 2;
        else          c = (len * (len + 1)) / 2;
        cnt[b] = c;
    }
    mx[t] = localmax;
    __syncthreads();
    if (t == 0) {
        int acc = 0;
        g_prefix[0] = 0;
        for (int b = 0; b < B; b++) { acc += cnt[b]; g_prefix[b + 1] = acc; }
        int m = 0;
        for (int k = 0; k < blockDim.x; k++) if (mx[k] > m) m = mx[k];
        g_maxlen = m;
    }
}

__global__ void __launch_bounds__(TPB)
span_fill_kernel(const int* __restrict__ seqs,
                 const int* __restrict__ lens,
                 const float* __restrict__ pw,
                 float* __restrict__ out,
                 int B, int S, int L, int N) {
    __shared__ int sp[MAXB + 1];
    __shared__ int sl[MAXB];
    __shared__ int rS[TPB];   // per-row start
    __shared__ int rB[TPB];   // per-row batch
    for (int k = threadIdx.x; k <= B; k += TPB) sp[k] = g_prefix[k];
    for (int k = threadIdx.x; k < B; k += TPB) sl[k] = lens[k];
    __syncthreads();

    const int tid = threadIdx.x;
    const int i = blockIdx.x * TPB + tid;
    const int total = sp[B];
    const int maxpos = g_maxlen - 1;
    const size_t Nz = (size_t)N;

    int b = 0, s = 0, l = 0;
    const bool valid = (i < N);

    if (valid) {
        // ---- row mapping: output row i -> (b, s, l) ----
        if (i < total) {
            int lo = 0, hi = B - 1;
            while (lo < hi) {
                int mid = (lo + hi + 1) >> 1;
                if (sp[mid] <= i) lo = mid; else hi = mid - 1;
            }
            b = lo;
            int j = i - sp[b];
            int len = sl[b];
            int full = len - L + 1;            // rows contributing L entries each
            if (full > 0 && j < full * L) {
                s = j / L;
                l = j - s * L;
            } else {
                int s0 = full > 0 ? full : 0;
                int jp = j - (full > 0 ? full * L : 0);
                int ss = s0, c = 0;
                while (true) {
                    int cnt = len - ss; if (cnt > L) cnt = L;
                    if (jp < c + cnt) { l = jp - c; break; }
                    c += cnt; ss++;
                }
                s = ss;
            }
        }
        // padding rows keep (b,s,l) = (0,0,0)

        // ---- candidate arrays (elementwise on i) + scalar outputs ----
        int SL = S * L;
        int bc = i / SL;
        int rem = i - bc * SL;
        int sc = rem / L;
        int lc = rem - sc * L;
        float viable_f = ((sc + lc) < sl[bc]) ? 1.0f : 0.0f;

        out[i]          = viable_f;
        out[Nz + i]     = (float)b;
        out[2 * Nz + i] = (float)s;
        out[3 * Nz + i] = (float)(s + l);
        out[4 * Nz + i] = (float)(l + 1);

        size_t off6 = 5 * Nz + Nz * (size_t)L;
        out[off6 + i]          = pw[((size_t)b * S + s) * L + l];
        out[off6 + Nz + i]     = (float)sc;
        out[off6 + 2 * Nz + i] = (float)(sc + lc);
        out[off6 + 3 * Nz + i] = (float)(lc + 1);
    }

    rS[tid] = s;   // padding / OOB threads contribute (0,0) -> harmless
    rB[tid] = b;
    __syncthreads();

    // ---- unit-id matrix: block-cooperative, fully contiguous stores ----
    // Block covers rows [base, base+nrows): nrows*L floats = nrows*5 float4s,
    // written contiguously (consecutive e -> consecutive 16B chunks).
    const int base_row = blockIdx.x * TPB;
    int nrows = N - base_row; if (nrows > TPB) nrows = TPB;
    float* ubase = out + 5 * Nz + (size_t)base_row * L;
    const int nchunks = nrows * 5;

    #pragma unroll
    for (int pass = 0; pass < 5; pass++) {
        int e = pass * TPB + tid;
        if (e < nchunks) {
            int r = e / 5;
            int j = (e - r * 5) << 2;       // float offset within row
            int s_r = rS[r];
            const int* row = seqs + (size_t)rB[r] * S;
            int p0 = s_r + j;     if (p0 > maxpos) p0 = maxpos;
            int p1 = s_r + j + 1; if (p1 > maxpos) p1 = maxpos;
            int p2 = s_r + j + 2; if (p2 > maxpos) p2 = maxpos;
            int p3 = s_r + j + 3; if (p3 > maxpos) p3 = maxpos;
            float4 v;
            v.x = (float)row[p0];
            v.y = (float)row[p1];
            v.z = (float)row[p2];
            v.w = (float)row[p3];
            *(float4*)(ubase + (size_t)r * L + j) = v;
        }
    }
}

extern "C" void kernel_launch(void* const* d_in, const int* in_sizes, int n_in,
                              void* d_out, int out_size) {
    const int* seqs = (const int*)d_in[0];   // (B, S) int32
    const int* lens = (const int*)d_in[1];   // (B,)   int32
    const float* pw = (const float*)d_in[2]; // (B, S, L) float32

    int B = in_sizes[1];
    int S = in_sizes[0] / B;
    int N = in_sizes[2];          // B*S*L
    int L = N / (B * S);
    float* out = (float*)d_out;

    span_scan_kernel<<<1, 256>>>(lens, B, L);
    int blocks = (N + TPB - 1) / TPB;
    span_fill_kernel<<<blocks, TPB>>>(seqs, lens, pw, out, B, S, L, N);
}

// round 3
// speedup vs baseline: 1.6519x; 1.1904x over previous
#include <cuda_runtime.h>
#include <cuda_bf16.h>

// BaseSpanProposer: analytic span compaction.
// viable[b,s,l] = (s + l) < len_b. nonzero order = ascending flattened index,
// computable in closed form via per-batch prefix sums. Padding rows -> flat 0.
//
// R2: unit-id stores transposed to block-cooperative contiguous float4 writes.
// R3: single fused kernel (per-block warp-shfl prefix scan, no scan launch),
//     compile-time S/L specialization (kills runtime int divides), __stcs
//     evict-first output stores.

#define MAXB 1024
#define TPB 256

template<int S_C, int L_C>
__global__ void __launch_bounds__(TPB)
span_fused_kernel(const int* __restrict__ seqs,
                  const int* __restrict__ lens,
                  const float* __restrict__ pw,
                  float* __restrict__ out,
                  int B, int S_rt, int L_rt, int N) {
    const int S = S_C ? S_C : S_rt;
    const int L = L_C ? L_C : L_rt;

    __shared__ int sp[TPB + 1];      // prefix sums (B <= TPB)
    __shared__ int sl[TPB];          // lens
    __shared__ int wsum[8];
    __shared__ int wmax[8];
    __shared__ int rBS[TPB];         // per-row packed (b<<16)|s

    const int tid = threadIdx.x;
    const int lane = tid & 31;
    const int warp = tid >> 5;

    // ---- per-block redundant prefix scan over per-batch viable counts ----
    int len = 0, cnt = 0;
    if (tid < B) {
        len = lens[tid];
        cnt = (len >= L) ? (len - L + 1) * L + (L * (L - 1)) / 2
                         : (len * (len + 1)) / 2;
    }
    int scn = cnt;
    #pragma unroll
    for (int o = 1; o < 32; o <<= 1) {
        int v = __shfl_up_sync(0xffffffffu, scn, o);
        if (lane >= o) scn += v;
    }
    int lmax = len;
    #pragma unroll
    for (int o = 16; o > 0; o >>= 1)
        lmax = max(lmax, __shfl_xor_sync(0xffffffffu, lmax, o));
    if (lane == 31) wsum[warp] = scn;
    if (lane == 0)  wmax[warp] = lmax;
    __syncthreads();
    int off = 0;
    #pragma unroll
    for (int k = 0; k < 8; k++) if (k < warp) off += wsum[k];
    if (tid < B) { sp[tid + 1] = scn + off; sl[tid] = len; }
    if (tid == 0) sp[0] = 0;
    int maxlen = 0;
    #pragma unroll
    for (int k = 0; k < 8; k++) maxlen = max(maxlen, wmax[k]);
    __syncthreads();

    const int i = blockIdx.x * TPB + tid;
    const int total = sp[B];
    const int maxpos = maxlen - 1;
    const size_t Nz = (size_t)N;

    int b = 0, s = 0, l = 0;
    if (i < N) {
        // ---- row mapping: output row i -> (b, s, l) ----
        if (i < total) {
            int lo = 0, hi = B - 1;
            while (lo < hi) {
                int mid = (lo + hi + 1) >> 1;
                if (sp[mid] <= i) lo = mid; else hi = mid - 1;
            }
            b = lo;
            int j = i - sp[b];
            int lb = sl[b];
            int full = lb - L + 1;          // starts contributing L entries each
            if (full > 0 && j < full * L) {
                s = j / L;
                l = j - s * L;
            } else {
                int s0 = full > 0 ? full : 0;
                int jp = j - (full > 0 ? full * L : 0);
                int ss = s0, c = 0;
                while (true) {
                    int m = lb - ss; if (m > L) m = L;
                    if (jp < c + m) { l = jp - c; break; }
                    c += m; ss++;
                }
                s = ss;
            }
        }
        // padding rows keep (b,s,l) = (0,0,0)

        // ---- candidate arrays (elementwise on i) + scalar outputs ----
        const int SL = S * L;
        int bc = i / SL;
        int rem = i - bc * SL;
        int sc = rem / L;
        int lc = rem - sc * L;
        float viable_f = ((sc + lc) < sl[bc]) ? 1.0f : 0.0f;

        __stcs(out + i,          viable_f);
        __stcs(out + Nz + i,     (float)b);
        __stcs(out + 2 * Nz + i, (float)s);
        __stcs(out + 3 * Nz + i, (float)(s + l));
        __stcs(out + 4 * Nz + i, (float)(l + 1));

        size_t off6 = 5 * Nz + Nz * (size_t)L;
        __stcs(out + off6 + i,          pw[((size_t)b * S + s) * L + l]);
        __stcs(out + off6 + Nz + i,     (float)sc);
        __stcs(out + off6 + 2 * Nz + i, (float)(sc + lc));
        __stcs(out + off6 + 3 * Nz + i, (float)(lc + 1));
    }

    rBS[tid] = (b << 16) | s;     // padding / OOB threads -> (0,0), harmless
    __syncthreads();

    // ---- unit-id matrix: block-cooperative, fully contiguous stores ----
    const int base_row = blockIdx.x * TPB;
    int nrows = N - base_row; if (nrows > TPB) nrows = TPB;
    float* ubase = out + 5 * Nz + (size_t)base_row * L;

    if (L == 20) {
        const int nchunks = nrows * 5;
        #pragma unroll
        for (int pass = 0; pass < 5; pass++) {
            int e = pass * TPB + tid;
            if (e < nchunks) {
                int r = e / 5;
                int j = (e - r * 5) << 2;
                int bs = rBS[r];
                int s_r = bs & 0xffff;
                const int* row = seqs + (size_t)(bs >> 16) * S;
                int p0 = s_r + j;     if (p0 > maxpos) p0 = maxpos;
                int p1 = s_r + j + 1; if (p1 > maxpos) p1 = maxpos;
                int p2 = s_r + j + 2; if (p2 > maxpos) p2 = maxpos;
                int p3 = s_r + j + 3; if (p3 > maxpos) p3 = maxpos;
                float4 v;
                v.x = (float)row[p0];
                v.y = (float)row[p1];
                v.z = (float)row[p2];
                v.w = (float)row[p3];
                __stcs((float4*)(ubase + (size_t)r * 20 + j), v);
            }
        }
    } else {
        // generic L path (scalar)
        for (int e = tid; e < nrows * L; e += TPB) {
            int r = e / L;
            int j = e - r * L;
            int bs = rBS[r];
            int p = (bs & 0xffff) + j; if (p > maxpos) p = maxpos;
            __stcs(ubase + (size_t)r * L + j,
                   (float)seqs[(size_t)(bs >> 16) * S + p]);
        }
    }
}

extern "C" void kernel_launch(void* const* d_in, const int* in_sizes, int n_in,
                              void* d_out, int out_size) {
    const int* seqs = (const int*)d_in[0];   // (B, S) int32
    const int* lens = (const int*)d_in[1];   // (B,)   int32
    const float* pw = (const float*)d_in[2]; // (B, S, L) float32

    int B = in_sizes[1];
    int S = in_sizes[0] / B;
    int N = in_sizes[2];          // B*S*L
    int L = N / (B * S);
    float* out = (float*)d_out;

    int blocks = (N + TPB - 1) / TPB;
    if (B <= TPB && S == 512 && L == 20) {
        span_fused_kernel<512, 20><<<blocks, TPB>>>(seqs, lens, pw, out, B, S, L, N);
    } else {
        // generic fallback (B must fit one block's scan; pad-safe for B<=TPB)
        span_fused_kernel<0, 0><<<blocks, TPB>>>(seqs, lens, pw, out, B, S, L, N);
    }
}